// round 3
// baseline (speedup 1.0000x reference)
#include <cuda_runtime.h>
#include <math.h>

#define CC 32
#define HH 256
#define WW 256
#define TW 64           // tile width = threads per block
#define TWP (TW + 2)    // with halo
#define KP 9
#define EPSF 1e-12f

__global__ __launch_bounds__(TW) void asfr_kernel(
    const float* __restrict__ fe,
    const float* __restrict__ fu,
    float* __restrict__ out)
{
    __shared__ float sm[CC * 3 * TWP];   // [CC][3][TWP] = 25,344 bytes

    const int tile = blockIdx.x;
    const int h    = blockIdx.y;
    const int b    = blockIdx.z;
    const int w0   = tile * TW;
    const int tid  = threadIdx.x;

    // ---- cooperative stage of fused 3-row x 32-ch x (TW+2) tile (zero-padded) ----
    const float* fub = fu + (size_t)b * CC * HH * WW;
    for (int idx = tid; idx < CC * 3 * TWP; idx += TW) {
        int c  = idx / (3 * TWP);
        int r  = idx - c * (3 * TWP);
        int dy = r / TWP;
        int j  = r - dy * TWP;
        int gy = h + dy - 1;
        int gx = w0 - 1 + j;
        float v = 0.0f;
        if (gy >= 0 && gy < HH && gx >= 0 && gx < WW)
            v = fub[(c * HH + gy) * WW + gx];
        sm[idx] = v;
    }
    __syncthreads();

    const int w = w0 + tid;
    const float* feb = fe + (((size_t)b * CC) * HH + h) * WW + w;

    // ---- pass 1: per-k dot(p,f) and ||p||^2, plus ||f||^2 ----
    float dot[KP], pn2[KP];
#pragma unroll
    for (int k = 0; k < KP; k++) { dot[k] = 0.0f; pn2[k] = 0.0f; }
    float fn2 = 0.0f;

#pragma unroll 4
    for (int c = 0; c < CC; c++) {
        float f = feb[c * HH * WW];
        fn2 = fmaf(f, f, fn2);
        const float* s = sm + c * (3 * TWP) + tid;
#pragma unroll
        for (int dy = 0; dy < 3; dy++) {
#pragma unroll
            for (int dx = 0; dx < 3; dx++) {
                float p = s[dy * TWP + dx];
                int k = dy * 3 + dx;
                dot[k] = fmaf(p, f, dot[k]);
                pn2[k] = fmaf(p, p, pn2[k]);
            }
        }
    }

    // ---- weights: 0.5*softmax(cos) + 0.5*softmax(-dist) ----
    float fn = fmaxf(sqrtf(fn2), EPSF);
    float cs[KP], ed[KP];
    float cmax = -1e30f, emax = -1e30f;
#pragma unroll
    for (int k = 0; k < KP; k++) {
        float pn = fmaxf(sqrtf(pn2[k]), EPSF);
        float c  = dot[k] / (pn * fn);
        float d2 = pn2[k] + fn2 - 2.0f * dot[k];
        float e  = -sqrtf(fmaxf(d2, 0.0f));
        cs[k] = c; ed[k] = e;
        cmax = fmaxf(cmax, c);
        emax = fmaxf(emax, e);
    }
    float csum = 0.0f, esum = 0.0f;
#pragma unroll
    for (int k = 0; k < KP; k++) {
        cs[k] = __expf(cs[k] - cmax); csum += cs[k];
        ed[k] = __expf(ed[k] - emax); esum += ed[k];
    }
    float ci = 0.5f / csum, ei = 0.5f / esum;
    float wgt[KP];
#pragma unroll
    for (int k = 0; k < KP; k++) wgt[k] = cs[k] * ci + ed[k] * ei;

    // ---- pass 2: refined = sum_k w_k * p_k ; out = refined + fe ----
    float* ob = out + (((size_t)b * CC) * HH + h) * WW + w;
#pragma unroll 4
    for (int c = 0; c < CC; c++) {
        float f = feb[c * HH * WW];   // L1 hit from pass 1
        const float* s = sm + c * (3 * TWP) + tid;
        float r = 0.0f;
#pragma unroll
        for (int dy = 0; dy < 3; dy++) {
#pragma unroll
            for (int dx = 0; dx < 3; dx++) {
                r = fmaf(wgt[dy * 3 + dx], s[dy * TWP + dx], r);
            }
        }
        ob[c * HH * WW] = r + f;
    }
}

extern "C" void kernel_launch(void* const* d_in, const int* in_sizes, int n_in,
                              void* d_out, int out_size)
{
    (void)in_sizes; (void)n_in; (void)out_size;
    const float* fe = (const float*)d_in[0];
    const float* fu = (const float*)d_in[1];
    float* out = (float*)d_out;

    dim3 grid(WW / TW, HH, 4);
    asfr_kernel<<<grid, TW>>>(fe, fu, out);
}